// round 14
// baseline (speedup 1.0000x reference)
#include <cuda_runtime.h>

// Problem constants (fixed: B=65536, T=100, D_CP=2, D_FIN=3, HID=12, D_OUT=2)
#define BT_B 65536
#define BT_T 100

typedef unsigned long long u64;

__device__ __forceinline__ u64 pack2(float lo, float hi) {
    u64 r; asm("mov.b64 %0, {%1, %2};" : "=l"(r) : "f"(lo), "f"(hi)); return r;
}
__device__ __forceinline__ void unpack2(u64 v, float& lo, float& hi) {
    asm("mov.b64 {%0, %1}, %2;" : "=f"(lo), "=f"(hi) : "l"(v));
}
__device__ __forceinline__ u64 fma2(u64 a, u64 b, u64 c) {
    u64 d; asm("fma.rn.f32x2 %0, %1, %2, %3;" : "=l"(d) : "l"(a), "l"(b), "l"(c)); return d;
}
__device__ __forceinline__ u64 mul2(u64 a, u64 b) {
    u64 d; asm("mul.rn.f32x2 %0, %1, %2;" : "=l"(d) : "l"(a), "l"(b)); return d;
}
__device__ __forceinline__ float tanhapx(float x) {
    float r; asm("tanh.approx.f32 %0, %1;" : "=f"(r) : "f"(x)); return r;
}

// Two threads per batch row (half ∈ {0,1} owns hidden units [6h,6h+6)).
// NEW: per-warp phase-stagger prologue. All warps run identical code and the
// RR arbiter keeps them phase-locked, so per-pipe bursts (MUFU.TANH, FMA)
// serialize instead of overlapping. A one-time per-warp delay offsets the
// phases so different warps exercise different pipes at any instant.
__global__ __launch_bounds__(128, 7)
void deform_tracker_kernel(const float* __restrict__ cp,     // (B, T, 2)
                           const float* __restrict__ fin,    // (B, T, 3)
                           const float* __restrict__ Wr,     // (5, 12)
                           const float* __restrict__ br,     // (12,)
                           const float* __restrict__ Wo,     // (14, 2)
                           const float* __restrict__ bo,     // (2,)
                           float* __restrict__ out)          // (B, T, 2)
{
    const int gt   = blockIdx.x * blockDim.x + threadIdx.x;  // 0 .. 131071
    const int row  = gt >> 1;
    const int half = gt & 1;
    const int cbase = 6 * half;

    // ---- Register-resident weights (own half of the hidden dim) ----
    u64 Wp[5][3];
    #pragma unroll
    for (int i = 0; i < 5; i++)
        #pragma unroll
        for (int k = 0; k < 3; k++)
            Wp[i][k] = pack2(__ldg(Wr + i * 12 + cbase + 2 * k),
                             __ldg(Wr + i * 12 + cbase + 2 * k + 1));

    u64 wup[3], wvp[3];
    #pragma unroll
    for (int k = 0; k < 3; k++) {
        wup[k] = pack2(__ldg(Wo + (2 + cbase + 2 * k) * 2 + 0),
                       __ldg(Wo + (3 + cbase + 2 * k) * 2 + 0));
        wvp[k] = pack2(__ldg(Wo + (2 + cbase + 2 * k) * 2 + 1),
                       __ldg(Wo + (3 + cbase + 2 * k) * 2 + 1));
    }
    const float w00 = __ldg(Wo + 0), w01 = __ldg(Wo + 1);
    const float w10 = __ldg(Wo + 2), w11 = __ldg(Wo + 3);
    const float bo0 = __ldg(bo + 0), bo1 = __ldg(bo + 1);

    // ---- Per-row invariants ----
    const float2 cp0 = *reinterpret_cast<const float2*>(cp + (size_t)row * (BT_T * 2));
    const float c0 = fmaf(cp0.x, w00, fmaf(cp0.y, w10, bo0));
    const float c1 = fmaf(cp0.x, w01, fmaf(cp0.y, w11, bo1));

    u64 base[3];
    {
        u64 p0 = pack2(c0, c0), p1 = pack2(c1, c1);
        #pragma unroll
        for (int k = 0; k < 3; k++) {
            u64 brp = pack2(__ldg(br + cbase + 2 * k), __ldg(br + cbase + 2 * k + 1));
            base[k] = fma2(p1, Wp[1][k], fma2(p0, Wp[0][k], brp));
        }
    }

    float u = cp0.x - c0, v = cp0.y - c1;

    const float2* fp = reinterpret_cast<const float2*>(fin + (size_t)row * (BT_T * 3));
    float4* op = reinterpret_cast<float4*>(out + (size_t)row * (BT_T * 2));

    // ---- Phase-stagger: offset this warp's loop phase vs other warps on the SM.
    // Slot = (CTA slot on SM) x 4 + (warp in CTA), spacing ~150 cycles.
    // One-time cost <= ~4.2K cycles; persists because all warps have identical
    // per-step timing afterwards. Output is unaffected.
    {
        const int slot = (int)((blockIdx.x % 7u) * 4u + (threadIdx.x >> 5));
        const unsigned long long delay = (unsigned long long)(slot * 150);
        const unsigned long long t0 = clock64();
        while (clock64() - t0 < delay) {}
    }

    // Depth-1 prefetch of the next chunk's finger data
    float2 nf0 = fp[0], nf1 = fp[1], nf2 = fp[2];

    #pragma unroll 1
    for (int c = 0; c < BT_T / 2; c++) {
        const float2 g0 = nf0, g1 = nf1, g2 = nf2;
        const int pc = (c < BT_T / 2 - 1) ? (c + 1) : c;   // clamp, no OOB
        nf0 = fp[3 * pc + 0];
        nf1 = fp[3 * pc + 1];
        nf2 = fp[3 * pc + 2];

        const float f[6] = {g0.x, g0.y, g1.x, g1.y, g2.x, g2.y};
        float res[4];

        #pragma unroll
        for (int s = 0; s < 2; s++) {
            // Off-chain partial (independent of u,v): base + fin_t @ Wr[2:5]
            u64 px2 = pack2(f[3 * s + 0], f[3 * s + 0]);
            u64 px3 = pack2(f[3 * s + 1], f[3 * s + 1]);
            u64 px4 = pack2(f[3 * s + 2], f[3 * s + 2]);
            u64 part[3];
            #pragma unroll
            for (int k = 0; k < 3; k++)
                part[k] = fma2(px4, Wp[4][k], fma2(px3, Wp[3][k], fma2(px2, Wp[2][k], base[k])));

            // Critical chain: + u*Wr0 + v*Wr1, tanh
            u64 pu = pack2(u, u), pv = pack2(v, v);
            float h[6];
            #pragma unroll
            for (int k = 0; k < 3; k++) {
                u64 a = fma2(pv, Wp[1][k], fma2(pu, Wp[0][k], part[k]));
                float a0, a1;
                unpack2(a, a0, a1);
                h[2 * k + 0] = tanhapx(a0);
                h[2 * k + 1] = tanhapx(a1);
            }

            // Packed output dot: uo = h . wu, vo = h . wv
            u64 hp0 = pack2(h[0], h[1]);
            u64 hp1 = pack2(h[2], h[3]);
            u64 hp2 = pack2(h[4], h[5]);
            u64 au = fma2(hp2, wup[2], fma2(hp1, wup[1], mul2(hp0, wup[0])));
            u64 av = fma2(hp2, wvp[2], fma2(hp1, wvp[1], mul2(hp0, wvp[0])));
            float ul, uh, vl, vh;
            unpack2(au, ul, uh);
            unpack2(av, vl, vh);
            float uo = ul + uh, vo = vl + vh;

            // Exchange partner's partial; both threads hold full (u,v)
            float up = __shfl_xor_sync(0xFFFFFFFFu, uo, 1);
            float vp = __shfl_xor_sync(0xFFFFFFFFu, vo, 1);
            u = uo + up;
            v = vo + vp;

            res[2 * s + 0] = c0 + u;
            res[2 * s + 1] = c1 + v;
        }

        // Alternate which pair-thread stores this chunk (lockstep-identical values)
        if (half == (c & 1)) {
            op[c] = make_float4(res[0], res[1], res[2], res[3]);
        }
    }
}

extern "C" void kernel_launch(void* const* d_in, const int* in_sizes, int n_in,
                              void* d_out, int out_size) {
    const float* cp  = (const float*)d_in[0];  // control_point_input (B,T,2)
    const float* fin = (const float*)d_in[1];  // finger_input (B,T,3)
    const float* Wr  = (const float*)d_in[2];  // W_rnn (5,12)
    // d_in[3] = U_rnn — mathematically inert (hidden state reset each step)
    const float* br  = (const float*)d_in[4];  // b_rnn (12,)
    const float* Wo  = (const float*)d_in[5];  // W_out (14,2)
    const float* bo  = (const float*)d_in[6];  // b_out (2,)
    float* out = (float*)d_out;

    const int threads = 128;
    const int total = BT_B * 2;                 // 2 threads per row
    const int blocks = total / threads;         // 1024 = one wave at 7 CTAs/SM
    deform_tracker_kernel<<<blocks, threads>>>(cp, fin, Wr, br, Wo, bo, out);
}

// round 15
// speedup vs baseline: 1.1057x; 1.1057x over previous
#include <cuda_runtime.h>
#include <cuda_fp16.h>

// Problem constants (fixed: B=65536, T=100, D_CP=2, D_FIN=3, HID=12, D_OUT=2)
#define BT_B 65536
#define BT_T 100

__device__ __forceinline__ __half2 htanh2(__half2 x) {
    unsigned xi = *reinterpret_cast<unsigned*>(&x), ri;
    asm("tanh.approx.f16x2 %0, %1;" : "=r"(ri) : "r"(xi));
    return *reinterpret_cast<__half2*>(&ri);
}

// One thread per batch row. Hidden-layer math (5x12 matmul, tanh, 12x2 dot) in
// fp16 (HFMA2 rt=2 for 2 lanes; tanh.approx.f16x2 = 2 tanh per MUFU op).
// Recurrent state (u,v), per-row constants, and outputs stay fp32.
__global__ __launch_bounds__(128, 4)
void deform_tracker_kernel(const float* __restrict__ cp,     // (B, T, 2)
                           const float* __restrict__ fin,    // (B, T, 3)
                           const float* __restrict__ Wr,     // (5, 12)
                           const float* __restrict__ br,     // (12,)
                           const float* __restrict__ Wo,     // (14, 2)
                           const float* __restrict__ bo,     // (2,)
                           float* __restrict__ out)          // (B, T, 2)
{
    const int row = blockIdx.x * blockDim.x + threadIdx.x;   // 0 .. 65535

    // ---- Weights in half2, register-resident. Wh[i][k] = (Wr[i][2k], Wr[i][2k+1]) ----
    __half2 Wh[5][6];
    #pragma unroll
    for (int i = 0; i < 5; i++)
        #pragma unroll
        for (int k = 0; k < 6; k++)
            Wh[i][k] = __halves2half2(__float2half_rn(__ldg(Wr + i * 12 + 2 * k)),
                                      __float2half_rn(__ldg(Wr + i * 12 + 2 * k + 1)));

    // Output weights per hidden pair: wu2[k] = (Wo[2+2k][0], Wo[3+2k][0]) etc.
    __half2 wu2[6], wv2[6];
    #pragma unroll
    for (int k = 0; k < 6; k++) {
        wu2[k] = __halves2half2(__float2half_rn(__ldg(Wo + (2 + 2 * k) * 2 + 0)),
                                __float2half_rn(__ldg(Wo + (3 + 2 * k) * 2 + 0)));
        wv2[k] = __halves2half2(__float2half_rn(__ldg(Wo + (2 + 2 * k) * 2 + 1)),
                                __float2half_rn(__ldg(Wo + (3 + 2 * k) * 2 + 1)));
    }
    const float w00 = __ldg(Wo + 0), w01 = __ldg(Wo + 1);
    const float w10 = __ldg(Wo + 2), w11 = __ldg(Wo + 3);
    const float bo0 = __ldg(bo + 0), bo1 = __ldg(bo + 1);

    // ---- Per-row invariants (fp32 precision for the constant parts) ----
    const float2 cp0 = *reinterpret_cast<const float2*>(cp + (size_t)row * (BT_T * 2));
    const float c0 = fmaf(cp0.x, w00, fmaf(cp0.y, w10, bo0));
    const float c1 = fmaf(cp0.x, w01, fmaf(cp0.y, w11, bo1));

    // base[j] = br[j] + c0*Wr0[j] + c1*Wr1[j] computed in fp32, then half2
    __half2 base2[6];
    #pragma unroll
    for (int k = 0; k < 6; k++) {
        float b0 = fmaf(c1, __ldg(Wr + 12 + 2 * k),
                   fmaf(c0, __ldg(Wr + 2 * k), __ldg(br + 2 * k)));
        float b1 = fmaf(c1, __ldg(Wr + 12 + 2 * k + 1),
                   fmaf(c0, __ldg(Wr + 2 * k + 1), __ldg(br + 2 * k + 1)));
        base2[k] = __halves2half2(__float2half_rn(b0), __float2half_rn(b1));
    }

    float u = cp0.x - c0, v = cp0.y - c1;   // o = (c0+u, c1+v); o_init = cp0

    const float2* fp = reinterpret_cast<const float2*>(fin + (size_t)row * (BT_T * 3));
    float4* op = reinterpret_cast<float4*>(out + (size_t)row * (BT_T * 2));

    // Depth-1 prefetch of the next chunk's finger data
    float2 nf0 = fp[0], nf1 = fp[1], nf2 = fp[2];

    #pragma unroll 1
    for (int c = 0; c < BT_T / 2; c++) {
        const float2 g0 = nf0, g1 = nf1, g2 = nf2;
        const int pc = (c < BT_T / 2 - 1) ? (c + 1) : c;   // clamp, no OOB
        nf0 = fp[3 * pc + 0];
        nf1 = fp[3 * pc + 1];
        nf2 = fp[3 * pc + 2];

        const float f[6] = {g0.x, g0.y, g1.x, g1.y, g2.x, g2.y};
        float res[4];

        #pragma unroll
        for (int s = 0; s < 2; s++) {
            // Broadcast inputs to half2 (1 cvt op each)
            const __half2 f2 = __float2half2_rn(f[3 * s + 0]);
            const __half2 f3 = __float2half2_rn(f[3 * s + 1]);
            const __half2 f4 = __float2half2_rn(f[3 * s + 2]);
            const __half2 u2 = __float2half2_rn(u);
            const __half2 v2 = __float2half2_rn(v);

            // a = base + f@Wr[2:5] + u*Wr0 + v*Wr1; h = tanh(a). All 12 units
            // as 6 half2 lanes; finger part is off the (u,v) critical chain.
            __half2 h2[6];
            #pragma unroll
            for (int k = 0; k < 6; k++) {
                __half2 a = __hfma2(f4, Wh[4][k],
                            __hfma2(f3, Wh[3][k],
                            __hfma2(f2, Wh[2][k], base2[k])));
                a = __hfma2(v2, Wh[1][k], __hfma2(u2, Wh[0][k], a));
                h2[k] = htanh2(a);
            }

            // Output dot in fp16 with split accumulators, fp32 final reduce
            __half2 pua = __hmul2(h2[0], wu2[0]), pub = __hmul2(h2[1], wu2[1]);
            __half2 pva = __hmul2(h2[0], wv2[0]), pvb = __hmul2(h2[1], wv2[1]);
            #pragma unroll
            for (int k = 2; k < 6; k += 2) {
                pua = __hfma2(h2[k],     wu2[k],     pua);
                pub = __hfma2(h2[k + 1], wu2[k + 1], pub);
                pva = __hfma2(h2[k],     wv2[k],     pva);
                pvb = __hfma2(h2[k + 1], wv2[k + 1], pvb);
            }
            const __half2 pu = __hadd2(pua, pub);
            const __half2 pv = __hadd2(pva, pvb);
            u = __half2float(__low2half(pu)) + __half2float(__high2half(pu));
            v = __half2float(__low2half(pv)) + __half2float(__high2half(pv));

            res[2 * s + 0] = c0 + u;
            res[2 * s + 1] = c1 + v;
        }

        op[c] = make_float4(res[0], res[1], res[2], res[3]);
    }
}

extern "C" void kernel_launch(void* const* d_in, const int* in_sizes, int n_in,
                              void* d_out, int out_size) {
    const float* cp  = (const float*)d_in[0];  // control_point_input (B,T,2)
    const float* fin = (const float*)d_in[1];  // finger_input (B,T,3)
    const float* Wr  = (const float*)d_in[2];  // W_rnn (5,12)
    // d_in[3] = U_rnn — mathematically inert (hidden state reset each step)
    const float* br  = (const float*)d_in[4];  // b_rnn (12,)
    const float* Wo  = (const float*)d_in[5];  // W_out (14,2)
    const float* bo  = (const float*)d_in[6];  // b_out (2,)
    float* out = (float*)d_out;

    const int threads = 128;
    const int blocks = BT_B / threads;          // 512 = one wave at 4 CTAs/SM
    deform_tracker_kernel<<<blocks, threads>>>(cp, fin, Wr, br, Wo, bo, out);
}

// round 16
// speedup vs baseline: 1.1921x; 1.0782x over previous
#include <cuda_runtime.h>
#include <cuda_fp16.h>

// Problem constants (fixed: B=65536, T=100, D_CP=2, D_FIN=3, HID=12, D_OUT=2)
#define BT_B 65536
#define BT_T 100

__device__ __forceinline__ __half2 htanh2(__half2 x) {
    unsigned xi = *reinterpret_cast<unsigned*>(&x), ri;
    asm("tanh.approx.f16x2 %0, %1;" : "=r"(ri) : "r"(xi));
    return *reinterpret_cast<__half2*>(&ri);
}

// Two threads per batch row (half ∈ {0,1} owns hidden units [6h, 6h+6) = 3 half2 lanes).
// Hidden-layer math in fp16 (HFMA2 + tanh.approx.f16x2); recurrent state (u,v),
// per-row constants and outputs in fp32. Partial dots exchanged via shfl.xor(1).
// 1024 blocks @ 7 CTAs/SM = one wave, ~7 warps/SMSP for latency hiding.
__global__ __launch_bounds__(128, 7)
void deform_tracker_kernel(const float* __restrict__ cp,     // (B, T, 2)
                           const float* __restrict__ fin,    // (B, T, 3)
                           const float* __restrict__ Wr,     // (5, 12)
                           const float* __restrict__ br,     // (12,)
                           const float* __restrict__ Wo,     // (14, 2)
                           const float* __restrict__ bo,     // (2,)
                           float* __restrict__ out)          // (B, T, 2)
{
    const int gt   = blockIdx.x * blockDim.x + threadIdx.x;  // 0 .. 131071
    const int row  = gt >> 1;
    const int half = gt & 1;
    const int cbase = 6 * half;

    // ---- Register-resident fp16 weights (own half of the hidden dim) ----
    __half2 Wh[5][3];
    #pragma unroll
    for (int i = 0; i < 5; i++)
        #pragma unroll
        for (int k = 0; k < 3; k++)
            Wh[i][k] = __halves2half2(
                __float2half_rn(__ldg(Wr + i * 12 + cbase + 2 * k)),
                __float2half_rn(__ldg(Wr + i * 12 + cbase + 2 * k + 1)));

    __half2 wu2[3], wv2[3];
    #pragma unroll
    for (int k = 0; k < 3; k++) {
        wu2[k] = __halves2half2(
            __float2half_rn(__ldg(Wo + (2 + cbase + 2 * k) * 2 + 0)),
            __float2half_rn(__ldg(Wo + (3 + cbase + 2 * k) * 2 + 0)));
        wv2[k] = __halves2half2(
            __float2half_rn(__ldg(Wo + (2 + cbase + 2 * k) * 2 + 1)),
            __float2half_rn(__ldg(Wo + (3 + cbase + 2 * k) * 2 + 1)));
    }
    const float w00 = __ldg(Wo + 0), w01 = __ldg(Wo + 1);
    const float w10 = __ldg(Wo + 2), w11 = __ldg(Wo + 3);
    const float bo0 = __ldg(bo + 0), bo1 = __ldg(bo + 1);

    // ---- Per-row invariants (fp32) ----
    const float2 cp0 = *reinterpret_cast<const float2*>(cp + (size_t)row * (BT_T * 2));
    const float c0 = fmaf(cp0.x, w00, fmaf(cp0.y, w10, bo0));
    const float c1 = fmaf(cp0.x, w01, fmaf(cp0.y, w11, bo1));

    // base[j] = br[j] + c0*Wr0[j] + c1*Wr1[j] in fp32, then to half2
    __half2 base2[3];
    #pragma unroll
    for (int k = 0; k < 3; k++) {
        const int j0 = cbase + 2 * k, j1 = j0 + 1;
        float b0 = fmaf(c1, __ldg(Wr + 12 + j0), fmaf(c0, __ldg(Wr + j0), __ldg(br + j0)));
        float b1 = fmaf(c1, __ldg(Wr + 12 + j1), fmaf(c0, __ldg(Wr + j1), __ldg(br + j1)));
        base2[k] = __halves2half2(__float2half_rn(b0), __float2half_rn(b1));
    }

    float u = cp0.x - c0, v = cp0.y - c1;   // o = (c0+u, c1+v); o_init = cp0

    const float2* fp = reinterpret_cast<const float2*>(fin + (size_t)row * (BT_T * 3));
    float4* op = reinterpret_cast<float4*>(out + (size_t)row * (BT_T * 2));

    // Depth-1 prefetch of the next chunk's finger data
    float2 nf0 = fp[0], nf1 = fp[1], nf2 = fp[2];

    #pragma unroll 1
    for (int c = 0; c < BT_T / 2; c++) {
        const float2 g0 = nf0, g1 = nf1, g2 = nf2;
        const int pc = (c < BT_T / 2 - 1) ? (c + 1) : c;   // clamp, no OOB
        nf0 = fp[3 * pc + 0];
        nf1 = fp[3 * pc + 1];
        nf2 = fp[3 * pc + 2];

        const float f[6] = {g0.x, g0.y, g1.x, g1.y, g2.x, g2.y};
        float res[4];

        #pragma unroll
        for (int s = 0; s < 2; s++) {
            // Broadcast inputs to half2
            const __half2 f2 = __float2half2_rn(f[3 * s + 0]);
            const __half2 f3 = __float2half2_rn(f[3 * s + 1]);
            const __half2 f4 = __float2half2_rn(f[3 * s + 2]);
            const __half2 u2 = __float2half2_rn(u);
            const __half2 v2 = __float2half2_rn(v);

            // a = base + f@Wr[2:5] + u*Wr0 + v*Wr1; h = tanh(a). 3 half2 lanes.
            // Finger part first (off the u,v critical chain).
            __half2 h2[3];
            #pragma unroll
            for (int k = 0; k < 3; k++) {
                __half2 a = __hfma2(f4, Wh[4][k],
                            __hfma2(f3, Wh[3][k],
                            __hfma2(f2, Wh[2][k], base2[k])));
                a = __hfma2(v2, Wh[1][k], __hfma2(u2, Wh[0][k], a));
                h2[k] = htanh2(a);
            }

            // Own half of the output dot in fp16, fp32 final reduce
            __half2 pu = __hfma2(h2[2], wu2[2],
                         __hfma2(h2[1], wu2[1], __hmul2(h2[0], wu2[0])));
            __half2 pv = __hfma2(h2[2], wv2[2],
                         __hfma2(h2[1], wv2[1], __hmul2(h2[0], wv2[0])));
            float uo = __half2float(__low2half(pu)) + __half2float(__high2half(pu));
            float vo = __half2float(__low2half(pv)) + __half2float(__high2half(pv));

            // Exchange partner's partial; both threads hold full (u,v)
            float up = __shfl_xor_sync(0xFFFFFFFFu, uo, 1);
            float vp = __shfl_xor_sync(0xFFFFFFFFu, vo, 1);
            u = uo + up;
            v = vo + vp;

            res[2 * s + 0] = c0 + u;
            res[2 * s + 1] = c1 + v;
        }

        // Alternate which pair-thread stores this chunk (lockstep-identical values)
        if (half == (c & 1)) {
            op[c] = make_float4(res[0], res[1], res[2], res[3]);
        }
    }
}

extern "C" void kernel_launch(void* const* d_in, const int* in_sizes, int n_in,
                              void* d_out, int out_size) {
    const float* cp  = (const float*)d_in[0];  // control_point_input (B,T,2)
    const float* fin = (const float*)d_in[1];  // finger_input (B,T,3)
    const float* Wr  = (const float*)d_in[2];  // W_rnn (5,12)
    // d_in[3] = U_rnn — mathematically inert (hidden state reset each step)
    const float* br  = (const float*)d_in[4];  // b_rnn (12,)
    const float* Wo  = (const float*)d_in[5];  // W_out (14,2)
    const float* bo  = (const float*)d_in[6];  // b_out (2,)
    float* out = (float*)d_out;

    const int threads = 128;
    const int total = BT_B * 2;                 // 2 threads per row
    const int blocks = total / threads;         // 1024 = one wave at 7 CTAs/SM
    deform_tracker_kernel<<<blocks, threads>>>(cp, fin, Wr, br, Wo, bo, out);
}

// round 17
// speedup vs baseline: 1.4225x; 1.1932x over previous
#include <cuda_runtime.h>
#include <cuda_fp16.h>

// Problem constants (fixed: B=65536, T=100, D_CP=2, D_FIN=3, HID=12, D_OUT=2)
#define BT_B 65536
#define BT_T 100

__device__ __forceinline__ __half2 htanh2(__half2 x) {
    unsigned xi = *reinterpret_cast<unsigned*>(&x), ri;
    asm("tanh.approx.f16x2 %0, %1;" : "=r"(ri) : "r"(xi));
    return *reinterpret_cast<__half2*>(&ri);
}

// Two threads per batch row (half ∈ {0,1} owns hidden units [6h, 6h+6) = 3 half2 lanes).
// fp16 hidden math (HFMA2 + tanh.approx.f16x2), fp32 state/outputs.
// 4-step chunks: 3x LDG.128 per chunk (halves load wavefronts vs float2) and
// ONE STG.128 per thread per chunk, pair threads storing adjacent float4s.
__global__ __launch_bounds__(128, 7)
void deform_tracker_kernel(const float* __restrict__ cp,     // (B, T, 2)
                           const float* __restrict__ fin,    // (B, T, 3)
                           const float* __restrict__ Wr,     // (5, 12)
                           const float* __restrict__ br,     // (12,)
                           const float* __restrict__ Wo,     // (14, 2)
                           const float* __restrict__ bo,     // (2,)
                           float* __restrict__ out)          // (B, T, 2)
{
    const int gt   = blockIdx.x * blockDim.x + threadIdx.x;  // 0 .. 131071
    const int row  = gt >> 1;
    const int half = gt & 1;
    const int cbase = 6 * half;

    // ---- Register-resident fp16 weights (own half of the hidden dim) ----
    __half2 Wh[5][3];
    #pragma unroll
    for (int i = 0; i < 5; i++)
        #pragma unroll
        for (int k = 0; k < 3; k++)
            Wh[i][k] = __halves2half2(
                __float2half_rn(__ldg(Wr + i * 12 + cbase + 2 * k)),
                __float2half_rn(__ldg(Wr + i * 12 + cbase + 2 * k + 1)));

    __half2 wu2[3], wv2[3];
    #pragma unroll
    for (int k = 0; k < 3; k++) {
        wu2[k] = __halves2half2(
            __float2half_rn(__ldg(Wo + (2 + cbase + 2 * k) * 2 + 0)),
            __float2half_rn(__ldg(Wo + (3 + cbase + 2 * k) * 2 + 0)));
        wv2[k] = __halves2half2(
            __float2half_rn(__ldg(Wo + (2 + cbase + 2 * k) * 2 + 1)),
            __float2half_rn(__ldg(Wo + (3 + cbase + 2 * k) * 2 + 1)));
    }
    const float w00 = __ldg(Wo + 0), w01 = __ldg(Wo + 1);
    const float w10 = __ldg(Wo + 2), w11 = __ldg(Wo + 3);
    const float bo0 = __ldg(bo + 0), bo1 = __ldg(bo + 1);

    // ---- Per-row invariants (fp32) ----
    const float2 cp0 = *reinterpret_cast<const float2*>(cp + (size_t)row * (BT_T * 2));
    const float c0 = fmaf(cp0.x, w00, fmaf(cp0.y, w10, bo0));
    const float c1 = fmaf(cp0.x, w01, fmaf(cp0.y, w11, bo1));

    // base[j] = br[j] + c0*Wr0[j] + c1*Wr1[j] in fp32, then to half2
    __half2 base2[3];
    #pragma unroll
    for (int k = 0; k < 3; k++) {
        const int j0 = cbase + 2 * k, j1 = j0 + 1;
        float b0 = fmaf(c1, __ldg(Wr + 12 + j0), fmaf(c0, __ldg(Wr + j0), __ldg(br + j0)));
        float b1 = fmaf(c1, __ldg(Wr + 12 + j1), fmaf(c0, __ldg(Wr + j1), __ldg(br + j1)));
        base2[k] = __halves2half2(__float2half_rn(b0), __float2half_rn(b1));
    }

    float u = cp0.x - c0, v = cp0.y - c1;   // o = (c0+u, c1+v); o_init = cp0

    const float4* fp4 = reinterpret_cast<const float4*>(fin + (size_t)row * (BT_T * 3)); // 75 float4
    float4* op = reinterpret_cast<float4*>(out + (size_t)row * (BT_T * 2));              // 50 float4

    // 25 chunks of 4 timesteps: 3 x LDG.128 in, 1 x STG.128 out per thread.
    #pragma unroll 1
    for (int c = 0; c < BT_T / 4; c++) {
        const float4 fa = fp4[3 * c + 0];
        const float4 fb = fp4[3 * c + 1];
        const float4 fc = fp4[3 * c + 2];
        const float f[12] = {fa.x, fa.y, fa.z, fa.w,
                             fb.x, fb.y, fb.z, fb.w,
                             fc.x, fc.y, fc.z, fc.w};
        float res[8];

        #pragma unroll
        for (int s = 0; s < 4; s++) {
            // Broadcast inputs to half2
            const __half2 f2 = __float2half2_rn(f[3 * s + 0]);
            const __half2 f3 = __float2half2_rn(f[3 * s + 1]);
            const __half2 f4 = __float2half2_rn(f[3 * s + 2]);
            const __half2 u2 = __float2half2_rn(u);
            const __half2 v2 = __float2half2_rn(v);

            // a = base + f@Wr[2:5] + u*Wr0 + v*Wr1; h = tanh(a). 3 half2 lanes.
            __half2 h2[3];
            #pragma unroll
            for (int k = 0; k < 3; k++) {
                __half2 a = __hfma2(f4, Wh[4][k],
                            __hfma2(f3, Wh[3][k],
                            __hfma2(f2, Wh[2][k], base2[k])));
                a = __hfma2(v2, Wh[1][k], __hfma2(u2, Wh[0][k], a));
                h2[k] = htanh2(a);
            }

            // Own half of the output dot in fp16, fp32 final reduce
            __half2 pu = __hfma2(h2[2], wu2[2],
                         __hfma2(h2[1], wu2[1], __hmul2(h2[0], wu2[0])));
            __half2 pv = __hfma2(h2[2], wv2[2],
                         __hfma2(h2[1], wv2[1], __hmul2(h2[0], wv2[0])));
            float uo = __half2float(__low2half(pu)) + __half2float(__high2half(pu));
            float vo = __half2float(__low2half(pv)) + __half2float(__high2half(pv));

            // Exchange partner's partial; both threads hold full (u,v)
            float up = __shfl_xor_sync(0xFFFFFFFFu, uo, 1);
            float vp = __shfl_xor_sync(0xFFFFFFFFu, vo, 1);
            u = uo + up;
            v = vo + vp;

            res[2 * s + 0] = c0 + u;
            res[2 * s + 1] = c1 + v;
        }

        // Pair threads store adjacent float4s: one STG.128 per thread per chunk,
        // warp covers 32B contiguous per row (lockstep-identical res values).
        const int rb = 4 * half;   // half0 -> res[0..3] (steps 0,1); half1 -> res[4..7]
        op[2 * c + half] = make_float4(res[rb + 0], res[rb + 1], res[rb + 2], res[rb + 3]);
    }
}

extern "C" void kernel_launch(void* const* d_in, const int* in_sizes, int n_in,
                              void* d_out, int out_size) {
    const float* cp  = (const float*)d_in[0];  // control_point_input (B,T,2)
    const float* fin = (const float*)d_in[1];  // finger_input (B,T,3)
    const float* Wr  = (const float*)d_in[2];  // W_rnn (5,12)
    // d_in[3] = U_rnn — mathematically inert (hidden state reset each step)
    const float* br  = (const float*)d_in[4];  // b_rnn (12,)
    const float* Wo  = (const float*)d_in[5];  // W_out (14,2)
    const float* bo  = (const float*)d_in[6];  // b_out (2,)
    float* out = (float*)d_out;

    const int threads = 128;
    const int total = BT_B * 2;                 // 2 threads per row
    const int blocks = total / threads;         // 1024 = one wave at 7 CTAs/SM
    deform_tracker_kernel<<<blocks, threads>>>(cp, fin, Wr, br, Wo, bo, out);
}